// round 4
// baseline (speedup 1.0000x reference)
#include <cuda_runtime.h>
#include <cuda_bf16.h>

#define NN 100000
#define NE 1000000
#define DI 128
#define DO 64
#define SB 1024
#define NBLK_SCAN ((NN + SB - 1) / SB)   // 98

// ---------------- scratch (device globals) ----------------------------------
__device__ float g_h0[NN * DO];
__device__ float g_h [NN * DO];
__device__ __nv_bfloat16 g_hb[NN * DO];   // bf16 copy of h for edge gathers
__device__ float g_A [NN * DO];
__device__ int   g_degd[NN];
__device__ int   g_degs[NN];
__device__ int   g_offd[NN + 1];
__device__ int   g_offs[NN + 1];
__device__ int   g_curd[NN];
__device__ int   g_curs[NN];
__device__ int   g_csrd[NE];     // src ids grouped by dst
__device__ int   g_csrs[NE];     // dst ids grouped by src
__device__ int   g_bsumd[NBLK_SCAN + 1];
__device__ int   g_bsums[NBLK_SCAN + 1];
__device__ float g_e[NN];
__device__ float g_nh[NN];
__device__ float g_q[NN];
__device__ float g_dinv[NN];
__device__ float g_pmax[256];
__device__ float g_pz[256];
__device__ float g_pw[256];
__device__ float g_scal[4];   // 0:m  1:1/Z  2:logZ  3:H

// ---------------- CSR build --------------------------------------------------
__global__ __launch_bounds__(256) void k_zero() {
    int i = blockIdx.x * 256 + threadIdx.x;
    if (i < NN) { g_degd[i] = 0; g_degs[i] = 0; }
}

__global__ __launch_bounds__(256) void k_deg(const int* __restrict__ ei) {
    int e = blockIdx.x * 256 + threadIdx.x;
    if (e >= NE) return;
    atomicAdd(&g_degs[ei[e]], 1);
    atomicAdd(&g_degd[ei[NE + e]], 1);
}

__global__ __launch_bounds__(SB) void k_scan1() {
    __shared__ int sd[SB], ss[SB];
    int t = threadIdx.x;
    int i = blockIdx.x * SB + t;
    int a = (i < NN) ? g_degd[i] : 0;
    int b = (i < NN) ? g_degs[i] : 0;
    sd[t] = a; ss[t] = b;
    __syncthreads();
    for (int o = 1; o < SB; o <<= 1) {
        int va = (t >= o) ? sd[t - o] : 0;
        int vb = (t >= o) ? ss[t - o] : 0;
        __syncthreads();
        sd[t] += va; ss[t] += vb;
        __syncthreads();
    }
    if (i < NN) { g_offd[i] = sd[t] - a; g_offs[i] = ss[t] - b; }
    if (t == SB - 1) { g_bsumd[blockIdx.x] = sd[t]; g_bsums[blockIdx.x] = ss[t]; }
}

__global__ __launch_bounds__(128) void k_scan2() {
    __shared__ int sd[128], ss[128];
    int t = threadIdx.x;
    int a = (t < NBLK_SCAN) ? g_bsumd[t] : 0;
    int b = (t < NBLK_SCAN) ? g_bsums[t] : 0;
    sd[t] = a; ss[t] = b;
    __syncthreads();
    for (int o = 1; o < 128; o <<= 1) {
        int va = (t >= o) ? sd[t - o] : 0;
        int vb = (t >= o) ? ss[t - o] : 0;
        __syncthreads();
        sd[t] += va; ss[t] += vb;
        __syncthreads();
    }
    if (t < NBLK_SCAN) { g_bsumd[t] = sd[t] - a; g_bsums[t] = ss[t] - b; }
}

__global__ __launch_bounds__(256) void k_scan3() {
    int i = blockIdx.x * 256 + threadIdx.x;
    if (i < NN) {
        int od = g_offd[i] + g_bsumd[i / SB];
        int os = g_offs[i] + g_bsums[i / SB];
        g_offd[i] = od; g_curd[i] = od;
        g_offs[i] = os; g_curs[i] = os;
        g_dinv[i] = rsqrtf((float)(g_degd[i] + 1));
    }
    if (i == 0) { g_offd[NN] = NE; g_offs[NN] = NE; }
}

__global__ __launch_bounds__(256) void k_fill(const int* __restrict__ ei) {
    int e = blockIdx.x * 256 + threadIdx.x;
    if (e >= NE) return;
    int s = ei[e], d = ei[NE + e];
    int pd = atomicAdd(&g_curd[d], 1);
    g_csrd[pd] = s;
    int ps = atomicAdd(&g_curs[s], 1);
    g_csrs[ps] = d;
}

// ---------------- GEMM: h0 = x @ W (128 rows/block, 8x8 per thread) ----------
__global__ __launch_bounds__(128) void k_gemm(const float* __restrict__ x,
                                              const float* __restrict__ W) {
    __shared__ float Ws[DI * DO];
    __shared__ float xs[16 * 128];
    int t = threadIdx.x;
    int row0 = blockIdx.x * 128;
    for (int i = t * 4; i < DI * DO; i += 128 * 4)
        *(float4*)(Ws + i) = *(const float4*)(W + i);

    int cg = t & 7, rt = t >> 3;
    float acc[8][8];
#pragma unroll
    for (int i = 0; i < 8; i++)
#pragma unroll
        for (int j = 0; j < 8; j++) acc[i][j] = 0.f;

    int grow = row0 + t;
    bool rok = grow < NN;

    for (int kc = 0; kc < 8; kc++) {
        __syncthreads();
        float4 xa = rok ? *(const float4*)(x + grow * DI + kc * 16 + 0)  : make_float4(0,0,0,0);
        float4 xb = rok ? *(const float4*)(x + grow * DI + kc * 16 + 4)  : make_float4(0,0,0,0);
        float4 xc = rok ? *(const float4*)(x + grow * DI + kc * 16 + 8)  : make_float4(0,0,0,0);
        float4 xd = rok ? *(const float4*)(x + grow * DI + kc * 16 + 12) : make_float4(0,0,0,0);
        xs[0*128+t]=xa.x;  xs[1*128+t]=xa.y;  xs[2*128+t]=xa.z;  xs[3*128+t]=xa.w;
        xs[4*128+t]=xb.x;  xs[5*128+t]=xb.y;  xs[6*128+t]=xb.z;  xs[7*128+t]=xb.w;
        xs[8*128+t]=xc.x;  xs[9*128+t]=xc.y;  xs[10*128+t]=xc.z; xs[11*128+t]=xc.w;
        xs[12*128+t]=xd.x; xs[13*128+t]=xd.y; xs[14*128+t]=xd.z; xs[15*128+t]=xd.w;
        __syncthreads();
#pragma unroll
        for (int k = 0; k < 16; k++) {
            float4 x0 = *(const float4*)(xs + k * 128 + rt * 8);
            float4 x1 = *(const float4*)(xs + k * 128 + rt * 8 + 4);
            float4 w0 = *(const float4*)(Ws + (kc * 16 + k) * DO + cg * 8);
            float4 w1 = *(const float4*)(Ws + (kc * 16 + k) * DO + cg * 8 + 4);
            float xv[8] = {x0.x, x0.y, x0.z, x0.w, x1.x, x1.y, x1.z, x1.w};
            float wv[8] = {w0.x, w0.y, w0.z, w0.w, w1.x, w1.y, w1.z, w1.w};
#pragma unroll
            for (int i = 0; i < 8; i++)
#pragma unroll
                for (int j = 0; j < 8; j++)
                    acc[i][j] += xv[i] * wv[j];
        }
    }
#pragma unroll
    for (int i = 0; i < 8; i++) {
        int gr = row0 + rt * 8 + i;
        if (gr < NN) {
            float4* p = (float4*)(g_h0 + gr * DO + cg * 8);
            p[0] = make_float4(acc[i][0], acc[i][1], acc[i][2], acc[i][3]);
            p[1] = make_float4(acc[i][4], acc[i][5], acc[i][6], acc[i][7]);
        }
    }
}

// ---------------- gather passes (16 lanes per node) ---------------------------
// pass1 (fp32): h_v = dinv_v * sum_{in(v)} h0_s*dinv_s + dinv_v^2*h0_v + b
// also writes bf16 copy of h and nh_v
__global__ __launch_bounds__(256) void k_pass1(const float* __restrict__ b) {
    int t = blockIdx.x * 256 + threadIdx.x;
    int v = t >> 4, q = t & 15;
    if (v >= NN) return;
    int start = g_offd[v], end = g_offd[v + 1];
    float ax = 0.f, ay = 0.f, az = 0.f, aw = 0.f;
    int idx = (start < end) ? g_csrd[start] : 0;
    for (int i = start; i < end; i++) {
        int nidx = (i + 1 < end) ? g_csrd[i + 1] : 0;
        float ds = g_dinv[idx];
        float4 u = *(const float4*)(g_h0 + idx * DO + q * 4);
        ax += u.x * ds; ay += u.y * ds; az += u.z * ds; aw += u.w * ds;
        idx = nidx;
    }
    float dv = g_dinv[v];
    float dv2 = dv * dv;
    float4 h0v = *(const float4*)(g_h0 + v * DO + q * 4);
    float4 bv  = *(const float4*)(b + q * 4);
    float4 h;
    h.x = dv * ax + dv2 * h0v.x + bv.x;
    h.y = dv * ay + dv2 * h0v.y + bv.y;
    h.z = dv * az + dv2 * h0v.z + bv.z;
    h.w = dv * aw + dv2 * h0v.w + bv.w;
    *(float4*)(g_h + v * DO + q * 4) = h;
    // bf16 copy
    __nv_bfloat162 b0 = __floats2bfloat162_rn(h.x, h.y);
    __nv_bfloat162 b1 = __floats2bfloat162_rn(h.z, h.w);
    uint2 pk;
    pk.x = *reinterpret_cast<unsigned int*>(&b0);
    pk.y = *reinterpret_cast<unsigned int*>(&b1);
    *(uint2*)(g_hb + v * DO + q * 4) = pk;
    float p = h.x * h.x + h.y * h.y + h.z * h.z + h.w * h.w;
#pragma unroll
    for (int off = 8; off; off >>= 1)
        p += __shfl_down_sync(0xffffffffu, p, off, 16);
    if (q == 0) g_nh[v] = p;
}

// pass2 (bf16 gather): A_v = sum h_s ; e_v = indeg*nh_v - 2*h_v.A_v + sum nh_s
__global__ __launch_bounds__(256) void k_pass2() {
    int t = blockIdx.x * 256 + threadIdx.x;
    int v = t >> 4, q = t & 15;
    if (v >= NN) return;
    int start = g_offd[v], end = g_offd[v + 1];
    float ax = 0.f, ay = 0.f, az = 0.f, aw = 0.f, es = 0.f;
    int idx = (start < end) ? g_csrd[start] : 0;
    for (int i = start; i < end; i++) {
        int nidx = (i + 1 < end) ? g_csrd[i + 1] : 0;
        uint2 pk = *(const uint2*)(g_hb + idx * DO + q * 4);
        float2 f0 = __bfloat1622float2(*reinterpret_cast<__nv_bfloat162*>(&pk.x));
        float2 f1 = __bfloat1622float2(*reinterpret_cast<__nv_bfloat162*>(&pk.y));
        ax += f0.x; ay += f0.y; az += f1.x; aw += f1.y;
        if (q == 0) es += g_nh[idx];
        idx = nidx;
    }
    *(float4*)(g_A + v * DO + q * 4) = make_float4(ax, ay, az, aw);
    float4 hv = *(const float4*)(g_h + v * DO + q * 4);
    float p = hv.x * ax + hv.y * ay + hv.z * az + hv.w * aw;
#pragma unroll
    for (int off = 8; off; off >>= 1)
        p += __shfl_down_sync(0xffffffffu, p, off, 16);
    if (q == 0)
        g_e[v] = (float)g_degd[v] * g_nh[v] - 2.f * p + es;
}

// ---------------- softmax scalars ---------------------------------------------
__global__ __launch_bounds__(256) void k_max(const float* __restrict__ temp) {
    float tmp = temp[0];
    float m = -1e30f;
    for (int i = blockIdx.x * 256 + threadIdx.x; i < NN; i += gridDim.x * 256)
        m = fmaxf(m, -g_e[i] / tmp);
    __shared__ float sm[256];
    sm[threadIdx.x] = m; __syncthreads();
    for (int o = 128; o; o >>= 1) {
        if (threadIdx.x < o) sm[threadIdx.x] = fmaxf(sm[threadIdx.x], sm[threadIdx.x + o]);
        __syncthreads();
    }
    if (threadIdx.x == 0) g_pmax[blockIdx.x] = sm[0];
}

__global__ __launch_bounds__(256) void k_maxfin() {
    __shared__ float sm[256];
    sm[threadIdx.x] = g_pmax[threadIdx.x];
    __syncthreads();
    for (int o = 128; o; o >>= 1) {
        if (threadIdx.x < o) sm[threadIdx.x] = fmaxf(sm[threadIdx.x], sm[threadIdx.x + o]);
        __syncthreads();
    }
    if (threadIdx.x == 0) g_scal[0] = sm[0];
}

__global__ __launch_bounds__(256) void k_sum(const float* __restrict__ temp) {
    float tmp = temp[0];
    float m = g_scal[0];
    float z = 0.f, w = 0.f;
    for (int i = blockIdx.x * 256 + threadIdx.x; i < NN; i += gridDim.x * 256) {
        float s = -g_e[i] / tmp - m;
        float ez = expf(s);
        z += ez; w += ez * s;
    }
    __shared__ float sz[256], sw[256];
    sz[threadIdx.x] = z; sw[threadIdx.x] = w; __syncthreads();
    for (int o = 128; o; o >>= 1) {
        if (threadIdx.x < o) {
            sz[threadIdx.x] += sz[threadIdx.x + o];
            sw[threadIdx.x] += sw[threadIdx.x + o];
        }
        __syncthreads();
    }
    if (threadIdx.x == 0) { g_pz[blockIdx.x] = sz[0]; g_pw[blockIdx.x] = sw[0]; }
}

__global__ __launch_bounds__(256) void k_sumfin() {
    __shared__ float sz[256], sw[256];
    sz[threadIdx.x] = g_pz[threadIdx.x];
    sw[threadIdx.x] = g_pw[threadIdx.x];
    __syncthreads();
    for (int o = 128; o; o >>= 1) {
        if (threadIdx.x < o) {
            sz[threadIdx.x] += sz[threadIdx.x + o];
            sw[threadIdx.x] += sw[threadIdx.x + o];
        }
        __syncthreads();
    }
    if (threadIdx.x == 0) {
        float Z = sz[0], Wm = sw[0];
        float logZ = logf(Z);
        g_scal[1] = 1.f / Z;
        g_scal[2] = logZ;
        g_scal[3] = logZ - Wm / Z;   // H
    }
}

__global__ __launch_bounds__(256) void k_q(const float* __restrict__ temp) {
    int v = blockIdx.x * 256 + threadIdx.x;
    if (v >= NN) return;
    float tmp = temp[0];
    float s = -g_e[v] / tmp - g_scal[0];
    float lp = s - g_scal[2];
    g_q[v] = expf(s) * g_scal[1] * (lp + g_scal[3]);
}

// pass3 (bf16 gather) + final: B_v = sum q_d h_d; Qs_v = sum q_d; write out
__global__ __launch_bounds__(256) void k_pass3(const float* __restrict__ wgt,
                                               float* __restrict__ out) {
    int t = blockIdx.x * 256 + threadIdx.x;
    int v = t >> 4, q = t & 15;
    if (v >= NN) return;
    int start = g_offs[v], end = g_offs[v + 1];
    float bx = 0.f, by = 0.f, bz = 0.f, bw = 0.f, Qs = 0.f;
    int idx = (start < end) ? g_csrs[start] : 0;
    for (int i = start; i < end; i++) {
        int nidx = (i + 1 < end) ? g_csrs[i + 1] : 0;
        float qd = g_q[idx];
        uint2 pk = *(const uint2*)(g_hb + idx * DO + q * 4);
        float2 f0 = __bfloat1622float2(*reinterpret_cast<__nv_bfloat162*>(&pk.x));
        float2 f1 = __bfloat1622float2(*reinterpret_cast<__nv_bfloat162*>(&pk.y));
        bx += qd * f0.x; by += qd * f0.y; bz += qd * f1.x; bw += qd * f1.y;
        Qs += qd;
        idx = nidx;
    }
    float4 hv = *(const float4*)(g_h + v * DO + q * 4);
    float4 Av = *(const float4*)(g_A + v * DO + q * 4);
    float qv = g_q[v];
    float dg = (float)g_degd[v];
    float w2 = 2.f * wgt[0];
    float4 o;
    o.x = hv.x + w2 * (qv * (dg * hv.x - Av.x) + Qs * hv.x - bx);
    o.y = hv.y + w2 * (qv * (dg * hv.y - Av.y) + Qs * hv.y - by);
    o.z = hv.z + w2 * (qv * (dg * hv.z - Av.z) + Qs * hv.z - bz);
    o.w = hv.w + w2 * (qv * (dg * hv.w - Av.w) + Qs * hv.w - bw);
    *(float4*)(out + v * DO + q * 4) = o;
}

// ---------------- launch ----------------------------------------------------
extern "C" void kernel_launch(void* const* d_in, const int* in_sizes, int n_in,
                              void* d_out, int out_size) {
    const float* x    = (const float*)d_in[0];
    const int*   ei   = (const int*)d_in[1];
    const float* wgt  = (const float*)d_in[2];
    const float* temp = (const float*)d_in[3];
    const float* W    = (const float*)d_in[4];
    const float* b    = (const float*)d_in[5];
    float* out = (float*)d_out;

    const int NB_E   = (NE + 255) / 256;
    const int NB_N   = (NN + 255) / 256;
    const int NB_N16 = (NN * 16 + 255) / 256;

    k_zero<<<NB_N, 256>>>();
    k_deg<<<NB_E, 256>>>(ei);
    k_scan1<<<NBLK_SCAN, SB>>>();
    k_scan2<<<1, 128>>>();
    k_scan3<<<NB_N, 256>>>();
    k_fill<<<NB_E, 256>>>(ei);
    k_gemm<<<(NN + 127) / 128, 128>>>(x, W);
    k_pass1<<<NB_N16, 256>>>(b);
    k_pass2<<<NB_N16, 256>>>();
    k_max<<<256, 256>>>(temp);
    k_maxfin<<<1, 256>>>();
    k_sum<<<256, 256>>>(temp);
    k_sumfin<<<1, 256>>>();
    k_q<<<NB_N, 256>>>(temp);
    k_pass3<<<NB_N16, 256>>>(wgt, out);
}

// round 5
// speedup vs baseline: 1.1260x; 1.1260x over previous
#include <cuda_runtime.h>

#define NN 100000
#define NE 1000000
#define DI 128
#define DO 64
#define SB 1024
#define NBLK_SCAN ((NN + SB - 1) / SB)   // 98
#define NSUMB 256

// ---------------- scratch (device globals) ----------------------------------
__device__ float g_h0[NN * DO];
__device__ float g_h [NN * DO];
__device__ float g_A [NN * DO];
__device__ int   g_degd[NN];
__device__ int   g_degs[NN];
__device__ int   g_offd[NN + 1];
__device__ int   g_offs[NN + 1];
__device__ int   g_curd[NN];
__device__ int   g_curs[NN];
__device__ int   g_csrd[NE];     // src ids grouped by dst
__device__ int   g_csrs[NE];     // dst ids grouped by src
__device__ int   g_bsumd[NBLK_SCAN + 1];
__device__ int   g_bsums[NBLK_SCAN + 1];
__device__ float g_e[NN];
__device__ float g_nh[NN];
__device__ float g_q[NN];
__device__ float g_dinv[NN];
__device__ float g_pm[NSUMB];
__device__ float g_pz[NSUMB];
__device__ float g_pt[NSUMB];

// ---------------- CSR build --------------------------------------------------
__global__ __launch_bounds__(256) void k_zero() {
    int i = blockIdx.x * 256 + threadIdx.x;
    if (i < NN) { g_degd[i] = 0; g_degs[i] = 0; }
}

__global__ __launch_bounds__(256) void k_deg(const int* __restrict__ ei) {
    int e = blockIdx.x * 256 + threadIdx.x;
    if (e >= NE) return;
    atomicAdd(&g_degs[ei[e]], 1);
    atomicAdd(&g_degd[ei[NE + e]], 1);
}

__global__ __launch_bounds__(SB) void k_scan1() {
    __shared__ int sd[SB], ss[SB];
    int t = threadIdx.x;
    int i = blockIdx.x * SB + t;
    int a = (i < NN) ? g_degd[i] : 0;
    int b = (i < NN) ? g_degs[i] : 0;
    sd[t] = a; ss[t] = b;
    __syncthreads();
    for (int o = 1; o < SB; o <<= 1) {
        int va = (t >= o) ? sd[t - o] : 0;
        int vb = (t >= o) ? ss[t - o] : 0;
        __syncthreads();
        sd[t] += va; ss[t] += vb;
        __syncthreads();
    }
    if (i < NN) { g_offd[i] = sd[t] - a; g_offs[i] = ss[t] - b; }
    if (t == SB - 1) { g_bsumd[blockIdx.x] = sd[t]; g_bsums[blockIdx.x] = ss[t]; }
}

__global__ __launch_bounds__(128) void k_scan2() {
    __shared__ int sd[128], ss[128];
    int t = threadIdx.x;
    int a = (t < NBLK_SCAN) ? g_bsumd[t] : 0;
    int b = (t < NBLK_SCAN) ? g_bsums[t] : 0;
    sd[t] = a; ss[t] = b;
    __syncthreads();
    for (int o = 1; o < 128; o <<= 1) {
        int va = (t >= o) ? sd[t - o] : 0;
        int vb = (t >= o) ? ss[t - o] : 0;
        __syncthreads();
        sd[t] += va; ss[t] += vb;
        __syncthreads();
    }
    if (t < NBLK_SCAN) { g_bsumd[t] = sd[t] - a; g_bsums[t] = sd[t] - a - (sd[t] - a) + ss[t] - b; }
}

__global__ __launch_bounds__(256) void k_scan3() {
    int i = blockIdx.x * 256 + threadIdx.x;
    if (i < NN) {
        int od = g_offd[i] + g_bsumd[i / SB];
        int os = g_offs[i] + g_bsums[i / SB];
        g_offd[i] = od; g_curd[i] = od;
        g_offs[i] = os; g_curs[i] = os;
        g_dinv[i] = rsqrtf((float)(g_degd[i] + 1));
    }
    if (i == 0) { g_offd[NN] = NE; g_offs[NN] = NE; }
}

__global__ __launch_bounds__(256) void k_fill(const int* __restrict__ ei) {
    int e = blockIdx.x * 256 + threadIdx.x;
    if (e >= NE) return;
    int s = ei[e], d = ei[NE + e];
    int pd = atomicAdd(&g_curd[d], 1);
    g_csrd[pd] = s;
    int ps = atomicAdd(&g_curs[s], 1);
    g_csrs[ps] = d;
}

// ---------------- GEMM: h0 = x @ W (128 rows/block, 8x8 per thread) ----------
__global__ __launch_bounds__(128) void k_gemm(const float* __restrict__ x,
                                              const float* __restrict__ W) {
    __shared__ float Ws[DI * DO];
    __shared__ float xs[16 * 128];
    int t = threadIdx.x;
    int row0 = blockIdx.x * 128;
    for (int i = t * 4; i < DI * DO; i += 128 * 4)
        *(float4*)(Ws + i) = *(const float4*)(W + i);

    int cg = t & 7, rt = t >> 3;
    float acc[8][8];
#pragma unroll
    for (int i = 0; i < 8; i++)
#pragma unroll
        for (int j = 0; j < 8; j++) acc[i][j] = 0.f;

    int grow = row0 + t;
    bool rok = grow < NN;

    for (int kc = 0; kc < 8; kc++) {
        __syncthreads();
        float4 xa = rok ? *(const float4*)(x + grow * DI + kc * 16 + 0)  : make_float4(0,0,0,0);
        float4 xb = rok ? *(const float4*)(x + grow * DI + kc * 16 + 4)  : make_float4(0,0,0,0);
        float4 xc = rok ? *(const float4*)(x + grow * DI + kc * 16 + 8)  : make_float4(0,0,0,0);
        float4 xd = rok ? *(const float4*)(x + grow * DI + kc * 16 + 12) : make_float4(0,0,0,0);
        xs[0*128+t]=xa.x;  xs[1*128+t]=xa.y;  xs[2*128+t]=xa.z;  xs[3*128+t]=xa.w;
        xs[4*128+t]=xb.x;  xs[5*128+t]=xb.y;  xs[6*128+t]=xb.z;  xs[7*128+t]=xb.w;
        xs[8*128+t]=xc.x;  xs[9*128+t]=xc.y;  xs[10*128+t]=xc.z; xs[11*128+t]=xc.w;
        xs[12*128+t]=xd.x; xs[13*128+t]=xd.y; xs[14*128+t]=xd.z; xs[15*128+t]=xd.w;
        __syncthreads();
#pragma unroll
        for (int k = 0; k < 16; k++) {
            float4 x0 = *(const float4*)(xs + k * 128 + rt * 8);
            float4 x1 = *(const float4*)(xs + k * 128 + rt * 8 + 4);
            float4 w0 = *(const float4*)(Ws + (kc * 16 + k) * DO + cg * 8);
            float4 w1 = *(const float4*)(Ws + (kc * 16 + k) * DO + cg * 8 + 4);
            float xv[8] = {x0.x, x0.y, x0.z, x0.w, x1.x, x1.y, x1.z, x1.w};
            float wv[8] = {w0.x, w0.y, w0.z, w0.w, w1.x, w1.y, w1.z, w1.w};
#pragma unroll
            for (int i = 0; i < 8; i++)
#pragma unroll
                for (int j = 0; j < 8; j++)
                    acc[i][j] += xv[i] * wv[j];
        }
    }
#pragma unroll
    for (int i = 0; i < 8; i++) {
        int gr = row0 + rt * 8 + i;
        if (gr < NN) {
            float4* p = (float4*)(g_h0 + gr * DO + cg * 8);
            p[0] = make_float4(acc[i][0], acc[i][1], acc[i][2], acc[i][3]);
            p[1] = make_float4(acc[i][4], acc[i][5], acc[i][6], acc[i][7]);
        }
    }
}

// ---------------- gather passes (16 lanes per node) ---------------------------
__global__ __launch_bounds__(256) void k_pass1(const float* __restrict__ b) {
    int t = blockIdx.x * 256 + threadIdx.x;
    int v = t >> 4, q = t & 15;
    if (v >= NN) return;
    int start = g_offd[v], end = g_offd[v + 1];
    float ax = 0.f, ay = 0.f, az = 0.f, aw = 0.f;
    int idx = (start < end) ? g_csrd[start] : 0;
    for (int i = start; i < end; i++) {
        int nidx = (i + 1 < end) ? g_csrd[i + 1] : 0;
        float ds = g_dinv[idx];
        float4 u = *(const float4*)(g_h0 + idx * DO + q * 4);
        ax += u.x * ds; ay += u.y * ds; az += u.z * ds; aw += u.w * ds;
        idx = nidx;
    }
    float dv = g_dinv[v];
    float dv2 = dv * dv;
    float4 h0v = *(const float4*)(g_h0 + v * DO + q * 4);
    float4 bv  = *(const float4*)(b + q * 4);
    float4 h;
    h.x = dv * ax + dv2 * h0v.x + bv.x;
    h.y = dv * ay + dv2 * h0v.y + bv.y;
    h.z = dv * az + dv2 * h0v.z + bv.z;
    h.w = dv * aw + dv2 * h0v.w + bv.w;
    *(float4*)(g_h + v * DO + q * 4) = h;
    float p = h.x * h.x + h.y * h.y + h.z * h.z + h.w * h.w;
#pragma unroll
    for (int off = 8; off; off >>= 1)
        p += __shfl_down_sync(0xffffffffu, p, off, 16);
    if (q == 0) g_nh[v] = p;
}

__global__ __launch_bounds__(256) void k_pass2() {
    int t = blockIdx.x * 256 + threadIdx.x;
    int v = t >> 4, q = t & 15;
    if (v >= NN) return;
    int start = g_offd[v], end = g_offd[v + 1];
    float ax = 0.f, ay = 0.f, az = 0.f, aw = 0.f, es = 0.f;
    int idx = (start < end) ? g_csrd[start] : 0;
    for (int i = start; i < end; i++) {
        int nidx = (i + 1 < end) ? g_csrd[i + 1] : 0;
        float4 hs = *(const float4*)(g_h + idx * DO + q * 4);
        ax += hs.x; ay += hs.y; az += hs.z; aw += hs.w;
        if (q == 0) es += g_nh[idx];
        idx = nidx;
    }
    *(float4*)(g_A + v * DO + q * 4) = make_float4(ax, ay, az, aw);
    float4 hv = *(const float4*)(g_h + v * DO + q * 4);
    float p = hv.x * ax + hv.y * ay + hv.z * az + hv.w * aw;
#pragma unroll
    for (int off = 8; off; off >>= 1)
        p += __shfl_down_sync(0xffffffffu, p, off, 16);
    if (q == 0)
        g_e[v] = (float)g_degd[v] * g_nh[v] - 2.f * p + es;
}

// ---------------- online softmax scalars --------------------------------------
// per-block online triple (m, z = sum exp(s-m), t = sum s*exp(s-m))
__device__ __forceinline__ void triple_merge(float& m, float& z, float& t,
                                             float m2, float z2, float t2) {
    float M = fmaxf(m, m2);
    float a = expf(m - M), c = expf(m2 - M);
    z = z * a + z2 * c;
    t = t * a + t2 * c;
    m = M;
}

__global__ __launch_bounds__(256) void k_sum(const float* __restrict__ temp) {
    float tmp = temp[0];
    float m = -1e30f, z = 0.f, t = 0.f;
    for (int i = blockIdx.x * 256 + threadIdx.x; i < NN; i += NSUMB * 256) {
        float s = -g_e[i] / tmp;
        float M = fmaxf(m, s);
        float a = expf(m - M), c = expf(s - M);
        z = z * a + c;
        t = t * a + s * c;
        m = M;
    }
    __shared__ float sm[256], sz[256], st[256];
    sm[threadIdx.x] = m; sz[threadIdx.x] = z; st[threadIdx.x] = t;
    __syncthreads();
    for (int o = 128; o; o >>= 1) {
        if (threadIdx.x < o) {
            float mm = sm[threadIdx.x], zz = sz[threadIdx.x], tt = st[threadIdx.x];
            triple_merge(mm, zz, tt, sm[threadIdx.x + o], sz[threadIdx.x + o], st[threadIdx.x + o]);
            sm[threadIdx.x] = mm; sz[threadIdx.x] = zz; st[threadIdx.x] = tt;
        }
        __syncthreads();
    }
    if (threadIdx.x == 0) {
        g_pm[blockIdx.x] = sm[0]; g_pz[blockIdx.x] = sz[0]; g_pt[blockIdx.x] = st[0];
    }
}

// combine NSUMB triples per block, then q for this block's slice
__global__ __launch_bounds__(256) void k_q(const float* __restrict__ temp) {
    __shared__ float sm[256], sz[256], st[256];
    int tx = threadIdx.x;
    sm[tx] = g_pm[tx]; sz[tx] = g_pz[tx]; st[tx] = g_pt[tx];
    __syncthreads();
    for (int o = 128; o; o >>= 1) {
        if (tx < o) {
            float mm = sm[tx], zz = sz[tx], tt = st[tx];
            triple_merge(mm, zz, tt, sm[tx + o], sz[tx + o], st[tx + o]);
            sm[tx] = mm; sz[tx] = zz; st[tx] = tt;
        }
        __syncthreads();
    }
    float M = sm[0], Z = sz[0], T = st[0];
    float invZ = 1.f / Z;
    float L = M + logf(Z);        // logsumexp
    float H = L - T * invZ;       // entropy
    int v = blockIdx.x * 256 + tx;
    if (v >= NN) return;
    float tmp = temp[0];
    float s = -g_e[v] / tmp;
    g_q[v] = expf(s - M) * invZ * (s - L + H);
}

// pass3 + final
__global__ __launch_bounds__(256) void k_pass3(const float* __restrict__ wgt,
                                               float* __restrict__ out) {
    int t = blockIdx.x * 256 + threadIdx.x;
    int v = t >> 4, q = t & 15;
    if (v >= NN) return;
    int start = g_offs[v], end = g_offs[v + 1];
    float bx = 0.f, by = 0.f, bz = 0.f, bw = 0.f, Qs = 0.f;
    int idx = (start < end) ? g_csrs[start] : 0;
    for (int i = start; i < end; i++) {
        int nidx = (i + 1 < end) ? g_csrs[i + 1] : 0;
        float qd = g_q[idx];
        float4 hd = *(const float4*)(g_h + idx * DO + q * 4);
        bx += qd * hd.x; by += qd * hd.y; bz += qd * hd.z; bw += qd * hd.w;
        Qs += qd;
        idx = nidx;
    }
    float4 hv = *(const float4*)(g_h + v * DO + q * 4);
    float4 Av = *(const float4*)(g_A + v * DO + q * 4);
    float qv = g_q[v];
    float dg = (float)g_degd[v];
    float w2 = 2.f * wgt[0];
    float4 o;
    o.x = hv.x + w2 * (qv * (dg * hv.x - Av.x) + Qs * hv.x - bx);
    o.y = hv.y + w2 * (qv * (dg * hv.y - Av.y) + Qs * hv.y - by);
    o.z = hv.z + w2 * (qv * (dg * hv.z - Av.z) + Qs * hv.z - bz);
    o.w = hv.w + w2 * (qv * (dg * hv.w - Av.w) + Qs * hv.w - bw);
    *(float4*)(out + v * DO + q * 4) = o;
}

// ---------------- launch ----------------------------------------------------
extern "C" void kernel_launch(void* const* d_in, const int* in_sizes, int n_in,
                              void* d_out, int out_size) {
    const float* x    = (const float*)d_in[0];
    const int*   ei   = (const int*)d_in[1];
    const float* wgt  = (const float*)d_in[2];
    const float* temp = (const float*)d_in[3];
    const float* W    = (const float*)d_in[4];
    const float* b    = (const float*)d_in[5];
    float* out = (float*)d_out;

    // one-time side stream + events (created on the eager correctness call)
    static cudaStream_t s2 = nullptr;
    static cudaEvent_t evA = nullptr, evB = nullptr;
    if (s2 == nullptr) {
        cudaStreamCreateWithFlags(&s2, cudaStreamNonBlocking);
        cudaEventCreateWithFlags(&evA, cudaEventDisableTiming);
        cudaEventCreateWithFlags(&evB, cudaEventDisableTiming);
    }

    const int NB_E   = (NE + 255) / 256;
    const int NB_N   = (NN + 255) / 256;
    const int NB_N16 = (NN * 16 + 255) / 256;

    // fork: GEMM on side stream, overlapped with CSR build
    cudaEventRecord(evA, 0);
    cudaStreamWaitEvent(s2, evA, 0);
    k_gemm<<<(NN + 127) / 128, 128, 0, s2>>>(x, W);
    cudaEventRecord(evB, s2);

    // CSR build on main stream
    k_zero<<<NB_N, 256>>>();
    k_deg<<<NB_E, 256>>>(ei);
    k_scan1<<<NBLK_SCAN, SB>>>();
    k_scan2<<<1, 128>>>();
    k_scan3<<<NB_N, 256>>>();
    k_fill<<<NB_E, 256>>>(ei);

    // join: pass1 needs both GEMM output and CSR
    cudaStreamWaitEvent(0, evB, 0);

    k_pass1<<<NB_N16, 256>>>(b);
    k_pass2<<<NB_N16, 256>>>();
    k_sum<<<NSUMB, 256>>>(temp);
    k_q<<<NB_N, 256>>>(temp);
    k_pass3<<<NB_N16, 256>>>(wgt, out);
}